// round 4
// baseline (speedup 1.0000x reference)
#include <cuda_runtime.h>
#include <math.h>

// EstimateAdj: out = diag(1/rowsum(A*B + I)) @ (A*B + I), N=8192.
// R4: 2 rows per CTA (grid=4096). One doubled load burst, one barrier for
//     both rows' reductions, one doubled store burst -> fewer per-row
//     pipeline bubbles and half the waves. Default caching (best measured).

#define N 8192
#define N4 (N / 4)            // 2048 float4 per row
#define TPB 512
#define V_PER_T (N4 / TPB)    // 4 float4 per thread per row
#define NWARPS (TPB / 32)     // 16
#define ROWS_PER_CTA 2

__global__ __launch_bounds__(TPB, 2)
void estimate_adj_kernel(const float4* __restrict__ A,
                         const float4* __restrict__ B,
                         float4* __restrict__ out) {
    const int row0 = blockIdx.x * ROWS_PER_CTA;
    const int row1 = row0 + 1;
    const long base0 = (long)row0 * N4;
    const long base1 = (long)row1 * N4;
    const int tid = threadIdx.x;

    float4 p0[V_PER_T], p1[V_PER_T];
    float sum0 = 0.0f, sum1 = 0.0f;

    // Doubled load burst: both rows' loads front-batched, branch-free.
    #pragma unroll
    for (int j = 0; j < V_PER_T; j++) {
        const int idx = tid + j * TPB;   // 0..2047
        float4 a0 = A[base0 + idx];
        float4 b0 = B[base0 + idx];
        float4 a1 = A[base1 + idx];
        float4 b1 = B[base1 + idx];
        float4 m0, m1;
        m0.x = a0.x * b0.x; m0.y = a0.y * b0.y;
        m0.z = a0.z * b0.z; m0.w = a0.w * b0.w;
        m1.x = a1.x * b1.x; m1.y = a1.y * b1.y;
        m1.z = a1.z * b1.z; m1.w = a1.w * b1.w;
        p0[j] = m0;
        p1[j] = m1;
        sum0 += (m0.x + m0.y) + (m0.z + m0.w);
        sum1 += (m1.x + m1.y) + (m1.z + m1.w);
    }

    // Warp reduction for both rows.
    #pragma unroll
    for (int off = 16; off > 0; off >>= 1) {
        sum0 += __shfl_xor_sync(0xFFFFFFFFu, sum0, off);
        sum1 += __shfl_xor_sync(0xFFFFFFFFu, sum1, off);
    }

    __shared__ float warp_sums0[NWARPS];
    __shared__ float warp_sums1[NWARPS];
    const int lane = tid & 31;
    const int wid = tid >> 5;
    if (lane == 0) {
        warp_sums0[wid] = sum0;
        warp_sums1[wid] = sum1;
    }
    __syncthreads();

    // Identity contributes +1 to every rowsum.
    float total0 = 1.0f, total1 = 1.0f;
    #pragma unroll
    for (int w = 0; w < NWARPS; w++) {
        total0 += warp_sums0[w];
        total1 += warp_sums1[w];
    }
    float rinv0 = 1.0f / total0;
    float rinv1 = 1.0f / total1;
    if (isinf(rinv0)) rinv0 = 0.0f;
    if (isinf(rinv1)) rinv1 = 0.0f;

    // Doubled store burst; diagonal fixup: out[r][r] += rinv.
    const int diag0 = row0 >> 2;
    const int diag1 = row1 >> 2;
    #pragma unroll
    for (int j = 0; j < V_PER_T; j++) {
        const int idx = tid + j * TPB;
        float4 m0 = p0[j];
        float4 m1 = p1[j];
        m0.x *= rinv0; m0.y *= rinv0; m0.z *= rinv0; m0.w *= rinv0;
        m1.x *= rinv1; m1.y *= rinv1; m1.z *= rinv1; m1.w *= rinv1;
        if (idx == diag0) ((float*)&m0)[row0 & 3] += rinv0;
        if (idx == diag1) ((float*)&m1)[row1 & 3] += rinv1;
        out[base0 + idx] = m0;
        out[base1 + idx] = m1;
    }
}

extern "C" void kernel_launch(void* const* d_in, const int* in_sizes, int n_in,
                              void* d_out, int out_size) {
    const float4* A = (const float4*)d_in[0];   // estimated_adj
    const float4* B = (const float4*)d_in[1];   // ori
    float4* out = (float4*)d_out;
    estimate_adj_kernel<<<N / ROWS_PER_CTA, TPB>>>(A, B, out);
}